// round 1
// baseline (speedup 1.0000x reference)
#include <cuda_runtime.h>

#define A 128
#define S 512
#define D 768
#define V 30522
#define NL 10
#define LW 5
#define MASK_ID 103

#define NCH 8          // attention s-chunks per row
#define CHUNK 64
#define JT 12          // dense j tiles (64 each)
#define KT 12          // dense k splits (128 each)
#define NTILE 64

// ---------------- scratch (device globals; no allocs allowed) ---------------
__device__ float g_m[A * NCH];
__device__ float g_l[A * NCH];
__device__ float g_acc[A * NCH * D];
__device__ float g_x[A * 2 * D];          // [att | mask_logit]
__device__ float g_hpart[KT * A * D];
__device__ float g_h[A * D];

// ---------------- kernel 1: mask_pos, senti_out, mask_logit copy ------------
__global__ void prep_kernel(const float* __restrict__ bert,
                            const int* __restrict__ ids,
                            const float* __restrict__ Wsen,
                            const float* __restrict__ bsen,
                            float* __restrict__ out) {
    int a = blockIdx.x, tid = threadIdx.x;
    __shared__ int mp;
    __shared__ float red0[8], red1[8];
    if (tid == 0) mp = S;
    __syncthreads();
    for (int s = tid; s < S; s += 256)
        if (ids[a * S + s] == MASK_ID) atomicMin(&mp, s);
    __syncthreads();
    int m = mp;
    const float* mlrow = bert + ((size_t)a * S + m) * D;
    for (int d = tid; d < D; d += 256)
        g_x[a * 2 * D + D + d] = mlrow[d];

    // senti_out = bert[a,0,:] @ W_senti.T + b_senti
    const float* r0 = bert + (size_t)a * S * D;
    float p0 = 0.f, p1 = 0.f;
    for (int d = tid; d < D; d += 256) {
        float v = r0[d];
        p0 = fmaf(v, Wsen[d], p0);
        p1 = fmaf(v, Wsen[D + d], p1);
    }
    #pragma unroll
    for (int off = 16; off; off >>= 1) {
        p0 += __shfl_xor_sync(0xffffffffu, p0, off);
        p1 += __shfl_xor_sync(0xffffffffu, p1, off);
    }
    int w = tid >> 5, lane = tid & 31;
    if (lane == 0) { red0[w] = p0; red1[w] = p1; }
    __syncthreads();
    if (tid == 0) {
        float s0 = 0.f, s1 = 0.f;
        #pragma unroll
        for (int i = 0; i < 8; i++) { s0 += red0[i]; s1 += red1[i]; }
        out[a * 2 + 0] = s0 + bsen[0];
        out[a * 2 + 1] = s1 + bsen[1];
    }
}

// ---------------- kernel 2: flash-style partial attention -------------------
__global__ void attn_partial(const float* __restrict__ bert,
                             const int* __restrict__ length) {
    int c = blockIdx.x, a = blockIdx.y, tid = threadIdx.x;
    int len = length[a];
    int s_lo = max(3, c * CHUNK);
    int s_hi = min((c + 1) * CHUNK, 3 + len);
    if (s_lo >= s_hi) {
        if (tid == 0) { g_m[a * NCH + c] = -1e30f; g_l[a * NCH + c] = 0.f; }
        return;
    }
    __shared__ __align__(16) float mls[D];
    __shared__ float sc[CHUNK];
    __shared__ float red[8];

    for (int d = tid; d < D; d += 256)
        mls[d] = g_x[a * 2 * D + D + d];
    __syncthreads();

    int warp = tid >> 5, lane = tid & 31;
    const float4* ml4 = (const float4*)mls;

    // phase 1: scores[s] = bert[a,s,:] . mask_logit  (one warp per s)
    for (int s = s_lo + warp; s < s_hi; s += 8) {
        const float4* row = (const float4*)(bert + ((size_t)a * S + s) * D);
        float acc = 0.f;
        #pragma unroll
        for (int k = 0; k < 6; k++) {
            float4 v = row[lane + 32 * k];
            float4 u = ml4[lane + 32 * k];
            acc = fmaf(v.x, u.x, acc); acc = fmaf(v.y, u.y, acc);
            acc = fmaf(v.z, u.z, acc); acc = fmaf(v.w, u.w, acc);
        }
        #pragma unroll
        for (int off = 16; off; off >>= 1)
            acc += __shfl_xor_sync(0xffffffffu, acc, off);
        if (lane == 0) sc[s - s_lo] = acc;
    }
    __syncthreads();

    // phase 2: local max + exp + sum
    int n = s_hi - s_lo;
    float mymax = -1e30f;
    for (int i = tid; i < n; i += 256) mymax = fmaxf(mymax, sc[i]);
    #pragma unroll
    for (int off = 16; off; off >>= 1)
        mymax = fmaxf(mymax, __shfl_xor_sync(0xffffffffu, mymax, off));
    if (lane == 0) red[warp] = mymax;
    __syncthreads();
    float M = red[0];
    #pragma unroll
    for (int i = 1; i < 8; i++) M = fmaxf(M, red[i]);
    __syncthreads();

    float mysum = 0.f;
    for (int i = tid; i < n; i += 256) {
        float e = expf(sc[i] - M);
        sc[i] = e;
        mysum += e;
    }
    #pragma unroll
    for (int off = 16; off; off >>= 1)
        mysum += __shfl_xor_sync(0xffffffffu, mysum, off);
    if (lane == 0) red[warp] = mysum;
    __syncthreads();
    float L = 0.f;
    #pragma unroll
    for (int i = 0; i < 8; i++) L += red[i];

    // phase 3: weighted accumulate (rows re-read hit L1: chunk <= 192KB)
    float a0 = 0.f, a1 = 0.f, a2 = 0.f;
    const float* base = bert + ((size_t)a * S + s_lo) * D;
    #pragma unroll 4
    for (int i = 0; i < n; i++) {
        float w = sc[i];
        const float* row = base + (size_t)i * D;
        a0 = fmaf(w, row[tid], a0);
        a1 = fmaf(w, row[tid + 256], a1);
        a2 = fmaf(w, row[tid + 512], a2);
    }
    size_t ob = (size_t)(a * NCH + c) * D;
    g_acc[ob + tid] = a0;
    g_acc[ob + tid + 256] = a1;
    g_acc[ob + tid + 512] = a2;
    if (tid == 0) { g_m[a * NCH + c] = M; g_l[a * NCH + c] = L; }
}

// ---------------- kernel 3: combine partial softmax, write att into x -------
__global__ void attn_combine() {
    int a = blockIdx.x, tid = threadIdx.x;
    __shared__ float sscale[NCH];
    __shared__ float sLinv;
    if (tid == 0) {
        float M = -1e30f;
        #pragma unroll
        for (int c = 0; c < NCH; c++) M = fmaxf(M, g_m[a * NCH + c]);
        float L = 0.f;
        #pragma unroll
        for (int c = 0; c < NCH; c++) {
            float lc = g_l[a * NCH + c];
            float s = (lc > 0.f) ? expf(g_m[a * NCH + c] - M) : 0.f;
            sscale[c] = s;
            L += lc * s;
        }
        sLinv = 1.f / L;
    }
    __syncthreads();
    float inv = sLinv;
    for (int d = tid; d < D; d += 256) {
        float v = 0.f;
        #pragma unroll
        for (int c = 0; c < NCH; c++)
            v = fmaf(g_acc[(size_t)(a * NCH + c) * D + d], sscale[c], v);
        g_x[a * 2 * D + d] = v * inv;
    }
}

// ---------------- kernel 4: dense GEMM split-K partials ---------------------
// h_pre[a,j] = sum_k x[a,k] * W_dense[j,k];  M=128, N=768, K=1536
__global__ void dense_partial(const float* __restrict__ Wd) {
    int jt = blockIdx.x;   // 0..11 -> j tile of 64
    int kt = blockIdx.y;   // 0..11 -> k slice of 128
    int tid = threadIdx.x;
    int j0 = jt * NTILE, k0 = kt * 128;
    __shared__ float xs[128][32];
    __shared__ float wst[32][NTILE + 1];
    int tj = tid & 31, tg = tid >> 5;
    float c0[16], c1[16];
    #pragma unroll
    for (int i = 0; i < 16; i++) { c0[i] = 0.f; c1[i] = 0.f; }

    for (int kk = 0; kk < 4; kk++) {
        __syncthreads();
        int kb = k0 + kk * 32;
        #pragma unroll
        for (int i = 0; i < 16; i++) {               // 128x32 x tile
            int idx = tid + i * 256;
            int aa = idx >> 5, k = idx & 31;
            xs[aa][k] = g_x[(size_t)aa * (2 * D) + kb + k];
        }
        #pragma unroll
        for (int i = 0; i < 8; i++) {                // 64x32 W tile, transposed
            int idx = tid + i * 256;
            int j = idx >> 5, k = idx & 31;
            wst[k][j] = Wd[(size_t)(j0 + j) * (2 * D) + kb + k];
        }
        __syncthreads();
        #pragma unroll
        for (int k = 0; k < 32; k++) {
            float w0 = wst[k][tj], w1 = wst[k][tj + 32];
            #pragma unroll
            for (int i = 0; i < 16; i++) {
                float xv = xs[tg + 8 * i][k];        // warp-broadcast
                c0[i] = fmaf(xv, w0, c0[i]);
                c1[i] = fmaf(xv, w1, c1[i]);
            }
        }
    }
    size_t base = (size_t)kt * A * D;
    #pragma unroll
    for (int i = 0; i < 16; i++) {
        int aa = tg + 8 * i;
        g_hpart[base + (size_t)aa * D + j0 + tj] = c0[i];
        g_hpart[base + (size_t)aa * D + j0 + 32 + tj] = c1[i];
    }
}

// ---------------- kernel 5: reduce split-K, bias, tanh ----------------------
__global__ void dense_finish(const float* __restrict__ bd) {
    int idx = blockIdx.x * 256 + threadIdx.x;   // < A*D
    int j = idx % D;
    float s = bd[j];
    #pragma unroll
    for (int t = 0; t < KT; t++) s += g_hpart[(size_t)t * A * D + idx];
    g_h[idx] = tanhf(s);
}

// ---------------- kernel 6: gathered vocab head + label einsum --------------
__global__ void head_kernel(const float* __restrict__ Wp,
                            const float* __restrict__ bp,
                            const int* __restrict__ lwords,
                            const float* __restrict__ Wlab,
                            float* __restrict__ out) {
    int a = blockIdx.x, tid = threadIdx.x;
    __shared__ __align__(16) float hs[D];
    __shared__ float lp[NL * LW];
    for (int d = tid; d < D; d += 256) hs[d] = g_h[a * D + d];
    __syncthreads();
    int warp = tid >> 5, lane = tid & 31;
    const float4* h4 = (const float4*)hs;
    for (int t = warp; t < NL * LW; t += 8) {
        int word = lwords[t];
        const float4* wr = (const float4*)(Wp + (size_t)word * D);
        float acc = 0.f;
        #pragma unroll
        for (int k = 0; k < 6; k++) {
            float4 v = wr[lane + 32 * k];
            float4 u = h4[lane + 32 * k];
            acc = fmaf(v.x, u.x, acc); acc = fmaf(v.y, u.y, acc);
            acc = fmaf(v.z, u.z, acc); acc = fmaf(v.w, u.w, acc);
        }
        #pragma unroll
        for (int off = 16; off; off >>= 1)
            acc += __shfl_xor_sync(0xffffffffu, acc, off);
        if (lane == 0) lp[t] = tanhf(acc + bp[word]);
    }
    __syncthreads();
    if (tid < 2 * NL) {
        int k = tid / NL, l = tid % NL;
        float o = 0.f;
        #pragma unroll
        for (int w = 0; w < LW; w++)
            o = fmaf(lp[l * LW + w], Wlab[(l * 2 + k) * LW + w], o);
        // out[a,k,l] row-major, after senti_out block
        out[2 * A + a * (2 * NL) + k * NL + l] = o;
    }
}

// ---------------------------------------------------------------------------
extern "C" void kernel_launch(void* const* d_in, const int* in_sizes, int n_in,
                              void* d_out, int out_size) {
    const float* bert   = (const float*)d_in[0];
    const int*   ids    = (const int*)d_in[1];
    const int*   length = (const int*)d_in[2];
    const int*   lwords = (const int*)d_in[3];
    const float* Wsen   = (const float*)d_in[4];
    const float* bsen   = (const float*)d_in[5];
    const float* Wd     = (const float*)d_in[6];
    const float* bd     = (const float*)d_in[7];
    const float* Wp     = (const float*)d_in[8];
    const float* bp     = (const float*)d_in[9];
    const float* Wlab   = (const float*)d_in[10];
    float* out = (float*)d_out;

    prep_kernel<<<A, 256>>>(bert, ids, Wsen, bsen, out);
    attn_partial<<<dim3(NCH, A), 256>>>(bert, length);
    attn_combine<<<A, 256>>>();
    dense_partial<<<dim3(JT, KT), 256>>>(Wd);
    dense_finish<<<(A * D) / 256, 256>>>(bd);
    head_kernel<<<A, 256>>>(Wp, bp, lwords, Wlab, out);
}